// round 1
// baseline (speedup 1.0000x reference)
#include <cuda_runtime.h>
#include <math.h>

#define L_SEQ 4096
#define BATCH 2
#define HID   1024
#define DHEAD 64
#define CHUNK 64
#define NCHUNK (L_SEQ / CHUNK)
#define GAMMA_F 0.96875f

// Scratch (allocation-free rule: __device__ globals)
__device__ float g_Q[BATCH * L_SEQ * DHEAD];
__device__ float g_K[BATCH * L_SEQ * DHEAD];
__device__ float g_V[BATCH * L_SEQ * DHEAD];
__device__ float g_A[BATCH * NCHUNK * DHEAD * DHEAD];  // per-chunk decayed K^T V
__device__ float g_S[BATCH * NCHUNK * DHEAD * DHEAD];  // state before each chunk

// ---------------------------------------------------------------------------
// Kernel 1: fused projection + xPos rotary scaling.
// C[8192 x 64] = X[8192 x 1024] @ W[1024 x 64], grid.y selects Q/K/V.
// BM=128, BN=64, BK=16, 256 threads, 8x4 microtile per thread.
// ---------------------------------------------------------------------------
__global__ __launch_bounds__(256) void proj_kernel(
    const float* __restrict__ X,
    const float* __restrict__ WQ,
    const float* __restrict__ WK,
    const float* __restrict__ WV) {
    const int which = blockIdx.y;   // 0=Q, 1=K, 2=V
    const float* __restrict__ W = (which == 0) ? WQ : ((which == 1) ? WK : WV);
    float* __restrict__ Out = (which == 0) ? g_Q : ((which == 1) ? g_K : g_V);

    __shared__ float Xs[16][132];   // [k][row], padded so rows are 16B-aligned
    __shared__ float Ws[16][64];    // [k][n]

    const int t  = threadIdx.x;
    const int m0 = blockIdx.x * 128;
    const int tx = t & 15;          // 16 column groups of 4
    const int ty = t >> 4;          // 16 row groups of 8

    float acc[8][4];
#pragma unroll
    for (int i = 0; i < 8; i++)
#pragma unroll
        for (int j = 0; j < 4; j++) acc[i][j] = 0.0f;

    const int lk = t & 15;          // k index for X loads
    const int lr = t >> 4;          // base row for X loads
    const int wn = t & 63;          // n index for W loads
    const int wk = t >> 6;          // base k for W loads

    for (int k0 = 0; k0 < HID; k0 += 16) {
#pragma unroll
        for (int i = 0; i < 8; i++)
            Xs[lk][lr + 16 * i] = X[(size_t)(m0 + lr + 16 * i) * HID + k0 + lk];
#pragma unroll
        for (int i = 0; i < 4; i++)
            Ws[wk + 4 * i][wn] = W[(size_t)(k0 + wk + 4 * i) * DHEAD + wn];
        __syncthreads();

#pragma unroll
        for (int kk = 0; kk < 16; kk++) {
            float a[8], b[4];
#pragma unroll
            for (int i = 0; i < 8; i++) a[i] = Xs[kk][ty * 8 + i];
#pragma unroll
            for (int j = 0; j < 4; j++) b[j] = Ws[kk][tx * 4 + j];
#pragma unroll
            for (int i = 0; i < 8; i++)
#pragma unroll
                for (int j = 0; j < 4; j++) acc[i][j] = fmaf(a[i], b[j], acc[i][j]);
        }
        __syncthreads();
    }

    // Epilogue: xPos rotary for Q (which==0) and K (which==1, downscale).
    const bool do_xpos = (which < 2);
    const bool down    = (which == 1);
#pragma unroll
    for (int i = 0; i < 8; i++) {
        const int m = m0 + ty * 8 + i;         // global row in [0, B*L)
        const int n = m & (L_SEQ - 1);         // sequence position
        if (do_xpos) {
            const float pf = (float)n;
#pragma unroll
            for (int jp = 0; jp < 2; jp++) {
                const int col = tx * 4 + jp * 2;      // even column
                const int hi  = col >> 1;             // half index 0..31
                const float sv = (2.0f * (float)hi + 0.4f * 64.0f) / (1.4f * 64.0f);
                float sc = powf(sv, pf / 512.0f);
                if (down) sc = 1.0f / sc;
                const float invf = powf(10000.0f, -((float)hi) / 32.0f);
                float s, c;
                sincosf(pf * invf, &s, &c);
                s *= sc; c *= sc;
                const float x0 = acc[i][jp * 2 + 0];
                const float x1 = acc[i][jp * 2 + 1];
                acc[i][jp * 2 + 0] = x0 * c - x1 * s;
                acc[i][jp * 2 + 1] = x1 * c + x0 * s;
            }
        }
#pragma unroll
        for (int j = 0; j < 4; j++)
            Out[(size_t)m * DHEAD + tx * 4 + j] = acc[i][j];
    }
}

// ---------------------------------------------------------------------------
// Kernel 2: per-chunk decayed state A_j[d1][d2] = sum_r gamma^(63-r) K[r][d1] V[r][d2]
// one block per (chunk, batch), 256 threads, each 4x4 entries.
// ---------------------------------------------------------------------------
__global__ __launch_bounds__(256) void chunk_stats_kernel() {
    const int j = blockIdx.x;
    const int b = blockIdx.y;
    __shared__ float Ks[CHUNK][DHEAD];   // pre-scaled by gamma^(63-r)
    __shared__ float Vs[CHUNK][DHEAD];

    const int t = threadIdx.x;
    const size_t base = (size_t)(b * L_SEQ + j * CHUNK) * DHEAD;
    for (int i = t; i < CHUNK * DHEAD; i += 256) {
        const int r = i >> 6, d = i & 63;
        const float w = powf(GAMMA_F, (float)(CHUNK - 1 - r));
        Ks[r][d] = g_K[base + i] * w;
        Vs[r][d] = g_V[base + i];
    }
    __syncthreads();

    const int ty = t >> 4, tx = t & 15;
    float acc[4][4];
#pragma unroll
    for (int i = 0; i < 4; i++)
#pragma unroll
        for (int jj = 0; jj < 4; jj++) acc[i][jj] = 0.0f;

    for (int r = 0; r < CHUNK; r++) {
        float a[4], v[4];
#pragma unroll
        for (int i = 0; i < 4; i++) a[i] = Ks[r][ty * 4 + i];
#pragma unroll
        for (int jj = 0; jj < 4; jj++) v[jj] = Vs[r][tx * 4 + jj];
#pragma unroll
        for (int i = 0; i < 4; i++)
#pragma unroll
            for (int jj = 0; jj < 4; jj++) acc[i][jj] = fmaf(a[i], v[jj], acc[i][jj]);
    }

    float* __restrict__ Ap = g_A + (size_t)(b * NCHUNK + j) * DHEAD * DHEAD;
#pragma unroll
    for (int i = 0; i < 4; i++)
#pragma unroll
        for (int jj = 0; jj < 4; jj++)
            Ap[(ty * 4 + i) * DHEAD + tx * 4 + jj] = acc[i][jj];
}

// ---------------------------------------------------------------------------
// Kernel 3: sequential scan over chunks: S_0 = 0; S_{j+1} = gamma^64 S_j + A_j.
// one block per batch, 1024 threads, 4 state elements each (in registers).
// ---------------------------------------------------------------------------
__global__ __launch_bounds__(1024) void scan_kernel() {
    const int b = blockIdx.x;
    const int t = threadIdx.x;
    float s0 = 0.f, s1 = 0.f, s2 = 0.f, s3 = 0.f;
    const float gC = powf(GAMMA_F, (float)CHUNK);
    for (int j = 0; j < NCHUNK; j++) {
        const size_t off = (size_t)(b * NCHUNK + j) * 4096;
        g_S[off + t]        = s0;
        g_S[off + t + 1024] = s1;
        g_S[off + t + 2048] = s2;
        g_S[off + t + 3072] = s3;
        s0 = gC * s0 + g_A[off + t];
        s1 = gC * s1 + g_A[off + t + 1024];
        s2 = gC * s2 + g_A[off + t + 2048];
        s3 = gC * s3 + g_A[off + t + 3072];
    }
}

// ---------------------------------------------------------------------------
// Kernel 4: per-chunk output.
// O[r] = sum_{r'<=r} gamma^(r-r') (q_r . k_r') v_r'  +  gamma^(r+1) q_r^T S_j
// one block per (chunk, batch), 256 threads, 4x4 O entries each.
// ---------------------------------------------------------------------------
__global__ __launch_bounds__(256) void out_kernel(float* __restrict__ O) {
    const int j = blockIdx.x;
    const int b = blockIdx.y;
    __shared__ float Qs[CHUNK][DHEAD + 1];
    __shared__ float Bs[CHUNK][DHEAD + 1];  // K, then V, then S
    __shared__ float Ps[CHUNK][DHEAD + 1];  // masked P = QK^T * decay
    __shared__ float gpow[CHUNK + 1];

    const int t = threadIdx.x;
    const size_t base = (size_t)(b * L_SEQ + j * CHUNK) * DHEAD;

    for (int i = t; i < CHUNK * DHEAD; i += 256) {
        const int r = i >> 6, d = i & 63;
        Qs[r][d] = g_Q[base + i];
        Bs[r][d] = g_K[base + i];
    }
    if (t < CHUNK + 1) gpow[t] = powf(GAMMA_F, (float)t);
    __syncthreads();

    const int ty = t >> 4, tx = t & 15;

    // Phase 1: P = (Q K^T) * decay-mask
    {
        float p[4][4];
#pragma unroll
        for (int i = 0; i < 4; i++)
#pragma unroll
            for (int jj = 0; jj < 4; jj++) p[i][jj] = 0.0f;
        for (int d = 0; d < DHEAD; d++) {
            float q[4], k[4];
#pragma unroll
            for (int i = 0; i < 4; i++) q[i] = Qs[ty * 4 + i][d];
#pragma unroll
            for (int jj = 0; jj < 4; jj++) k[jj] = Bs[tx * 4 + jj][d];
#pragma unroll
            for (int i = 0; i < 4; i++)
#pragma unroll
                for (int jj = 0; jj < 4; jj++) p[i][jj] = fmaf(q[i], k[jj], p[i][jj]);
        }
#pragma unroll
        for (int i = 0; i < 4; i++) {
            const int r = ty * 4 + i;
#pragma unroll
            for (int jj = 0; jj < 4; jj++) {
                const int rp = tx * 4 + jj;
                Ps[r][rp] = (r >= rp) ? p[i][jj] * gpow[r - rp] : 0.0f;
            }
        }
    }
    __syncthreads();

    // Phase 2: O = P @ V  (V overwrites K slot)
    for (int i = t; i < CHUNK * DHEAD; i += 256)
        Bs[i >> 6][i & 63] = g_V[base + i];
    __syncthreads();

    float o[4][4];
#pragma unroll
    for (int i = 0; i < 4; i++)
#pragma unroll
        for (int jj = 0; jj < 4; jj++) o[i][jj] = 0.0f;

    for (int r2 = 0; r2 < CHUNK; r2++) {
        float pp[4], v[4];
#pragma unroll
        for (int i = 0; i < 4; i++) pp[i] = Ps[ty * 4 + i][r2];
#pragma unroll
        for (int jj = 0; jj < 4; jj++) v[jj] = Bs[r2][tx * 4 + jj];
#pragma unroll
        for (int i = 0; i < 4; i++)
#pragma unroll
            for (int jj = 0; jj < 4; jj++) o[i][jj] = fmaf(pp[i], v[jj], o[i][jj]);
    }
    __syncthreads();

    // Phase 3: cross-chunk O += gamma^(r+1) * (Q @ S_j)   (S overwrites slot)
    {
        const size_t soff = (size_t)(b * NCHUNK + j) * 4096;
        for (int i = t; i < CHUNK * DHEAD; i += 256)
            Bs[i >> 6][i & 63] = g_S[soff + i];
    }
    __syncthreads();

    float cc[4][4];
#pragma unroll
    for (int i = 0; i < 4; i++)
#pragma unroll
        for (int jj = 0; jj < 4; jj++) cc[i][jj] = 0.0f;

    for (int d2 = 0; d2 < DHEAD; d2++) {
        float q[4], s[4];
#pragma unroll
        for (int i = 0; i < 4; i++) q[i] = Qs[ty * 4 + i][d2];
#pragma unroll
        for (int jj = 0; jj < 4; jj++) s[jj] = Bs[d2][tx * 4 + jj];
#pragma unroll
        for (int i = 0; i < 4; i++)
#pragma unroll
            for (int jj = 0; jj < 4; jj++) cc[i][jj] = fmaf(q[i], s[jj], cc[i][jj]);
    }

#pragma unroll
    for (int i = 0; i < 4; i++) {
        const int r = ty * 4 + i;
        const float g = gpow[r + 1];
        const size_t orow = (size_t)(b * L_SEQ + j * CHUNK + r) * DHEAD;
#pragma unroll
        for (int jj = 0; jj < 4; jj++)
            O[orow + tx * 4 + jj] = o[i][jj] + g * cc[i][jj];
    }
}

// ---------------------------------------------------------------------------
extern "C" void kernel_launch(void* const* d_in, const int* in_sizes, int n_in,
                              void* d_out, int out_size) {
    const float* X  = (const float*)d_in[0];
    const float* WQ = (const float*)d_in[1];
    const float* WK = (const float*)d_in[2];
    const float* WV = (const float*)d_in[3];
    float* O = (float*)d_out;

    proj_kernel<<<dim3((BATCH * L_SEQ) / 128, 3), 256>>>(X, WQ, WK, WV);
    chunk_stats_kernel<<<dim3(NCHUNK, BATCH), 256>>>();
    scan_kernel<<<BATCH, 1024>>>();
    out_kernel<<<dim3(NCHUNK, BATCH), 256>>>(O);
}

// round 5
// speedup vs baseline: 1.5826x; 1.5826x over previous
#include <cuda_runtime.h>
#include <cuda_bf16.h>
#include <stdint.h>
#include <math.h>

#define L_SEQ 4096
#define BATCH 2
#define HID   1024
#define DHEAD 64
#define CHUNK 64
#define NCHUNK (L_SEQ / CHUNK)
#define GAMMA_F 0.96875f
#define SDEPTH 16   // gamma^(64*16) ~ 7e-15: below fp32 noise

// Scratch (allocation-free rule: __device__ globals)
__device__ float g_Q[BATCH * L_SEQ * DHEAD];
__device__ float g_K[BATCH * L_SEQ * DHEAD];
__device__ float g_V[BATCH * L_SEQ * DHEAD];
__device__ float g_A[BATCH * NCHUNK * DHEAD * DHEAD];
__device__ float g_S[BATCH * NCHUNK * DHEAD * DHEAD];

#define MMA16816(d, a, b)                                                   \
    asm volatile(                                                           \
        "mma.sync.aligned.m16n8k16.row.col.f32.bf16.bf16.f32 "              \
        "{%0,%1,%2,%3}, {%4,%5,%6,%7}, {%8,%9}, {%0,%1,%2,%3};\n"           \
        : "+f"(d[0]), "+f"(d[1]), "+f"(d[2]), "+f"(d[3])                    \
        : "r"(a[0]), "r"(a[1]), "r"(a[2]), "r"(a[3]), "r"(b[0]), "r"(b[1]))

// ---------------------------------------------------------------------------
// Kernel 1: projection via bf16 split-MMA + fused xPos epilogue.
// C[8192x64] = X[8192x1024] @ W[1024x64].  BM=64, BN=64, BK=32, 8 warps.
// Warp tile 16(m) x 32(n).  3-pass hi/lo compensation for fp32-class accuracy.
// ---------------------------------------------------------------------------
__global__ __launch_bounds__(256) void proj_mma_kernel(
    const float* __restrict__ X,
    const float* __restrict__ WQ,
    const float* __restrict__ WK,
    const float* __restrict__ WV) {
    const int which = blockIdx.y;   // 0=Q, 1=K, 2=V
    const float* __restrict__ W = (which == 0) ? WQ : ((which == 1) ? WK : WV);
    float* __restrict__ Out = (which == 0) ? g_Q : ((which == 1) ? g_K : g_V);

    __shared__ __nv_bfloat16 Ah[64][40];   // pad 8 -> conflict-free frag loads
    __shared__ __nv_bfloat16 Al[64][40];
    __shared__ __nv_bfloat16 Bh[64][40];   // W transposed: [n][k]
    __shared__ __nv_bfloat16 Bl[64][40];

    const int t    = threadIdx.x;
    const int warp = t >> 5, lane = t & 31;
    const int grp  = lane >> 2, tig = lane & 3;
    const int wm   = warp >> 1;            // 0..3: 16-row tile
    const int wn   = warp & 1;             // 0..1: 32-col tile
    const int m0   = blockIdx.x * 64;

    float acc[4][4];
#pragma unroll
    for (int nt = 0; nt < 4; nt++)
#pragma unroll
        for (int c = 0; c < 4; c++) acc[nt][c] = 0.0f;

    const int xr = t >> 3;          // 0..31
    const int xc = (t & 7) * 4;     // 0..28

    for (int k0 = 0; k0 < HID; k0 += 32) {
        // --- load + split X tile (64x32 fp32) ---
#pragma unroll
        for (int i = 0; i < 2; i++) {
            const int row = i * 32 + xr;
            float4 v = *(const float4*)(X + (size_t)(m0 + row) * HID + k0 + xc);
            float vv[4] = {v.x, v.y, v.z, v.w};
#pragma unroll
            for (int e = 0; e < 4; e++) {
                __nv_bfloat16 h = __float2bfloat16(vv[e]);
                Ah[row][xc + e] = h;
                Al[row][xc + e] = __float2bfloat16(vv[e] - __bfloat162float(h));
            }
        }
        // --- load + split + transpose W tile (32x64 fp32 -> [n][k]) ---
#pragma unroll
        for (int i = 0; i < 8; i++) {
            const int idx = t + i * 256;
            const int kk = idx >> 6, n = idx & 63;
            float v = W[(size_t)(k0 + kk) * DHEAD + n];
            __nv_bfloat16 h = __float2bfloat16(v);
            Bh[n][kk] = h;
            Bl[n][kk] = __float2bfloat16(v - __bfloat162float(h));
        }
        __syncthreads();

#pragma unroll
        for (int ks = 0; ks < 32; ks += 16) {
            const int r = wm * 16 + grp;
            const int c = ks + tig * 2;
            uint32_t ah[4], al[4];
            ah[0] = *(const uint32_t*)&Ah[r][c];
            ah[1] = *(const uint32_t*)&Ah[r + 8][c];
            ah[2] = *(const uint32_t*)&Ah[r][c + 8];
            ah[3] = *(const uint32_t*)&Ah[r + 8][c + 8];
            al[0] = *(const uint32_t*)&Al[r][c];
            al[1] = *(const uint32_t*)&Al[r + 8][c];
            al[2] = *(const uint32_t*)&Al[r][c + 8];
            al[3] = *(const uint32_t*)&Al[r + 8][c + 8];
            uint32_t bh[4][2], bl[4][2];
#pragma unroll
            for (int nt = 0; nt < 4; nt++) {
                const int n = wn * 32 + nt * 8 + grp;
                bh[nt][0] = *(const uint32_t*)&Bh[n][c];
                bh[nt][1] = *(const uint32_t*)&Bh[n][c + 8];
                bl[nt][0] = *(const uint32_t*)&Bl[n][c];
                bl[nt][1] = *(const uint32_t*)&Bl[n][c + 8];
            }
#pragma unroll
            for (int nt = 0; nt < 4; nt++) {
                MMA16816(acc[nt], ah, bh[nt]);
                MMA16816(acc[nt], ah, bl[nt]);
                MMA16816(acc[nt], al, bh[nt]);
            }
        }
        __syncthreads();
    }

    // --- epilogue: xPos rotary for Q (which=0) / K (which=1, downscale) ---
    const bool dox  = (which < 2);
    const bool down = (which == 1);
#pragma unroll
    for (int nt = 0; nt < 4; nt++) {
        const int col = wn * 32 + nt * 8 + tig * 2;   // even column of pair
        const int h   = col >> 1;                      // half index 0..31
        float lsv = 0.f, invf = 0.f;
        if (dox) {
            lsv  = __log2f(((float)col + 25.6f) / 89.6f);
            invf = exp2f((float)h * (-13.287712379549449f / 32.0f));
        }
#pragma unroll
        for (int half = 0; half < 2; half++) {
            const int rr = m0 + wm * 16 + grp + half * 8;
            float x0 = acc[nt][half * 2 + 0];
            float x1 = acc[nt][half * 2 + 1];
            if (dox) {
                const float pos = (float)(rr & (L_SEQ - 1));
                float e = lsv * pos * (1.0f / 512.0f);
                if (down) e = -e;
                const float sc = exp2f(e);
                float s, cg;
                sincosf(pos * invf, &s, &cg);
                s *= sc; cg *= sc;
                const float y0 = x0 * cg - x1 * s;
                const float y1 = x1 * cg + x0 * s;
                x0 = y0; x1 = y1;
            }
            *(float2*)(Out + (size_t)rr * DHEAD + col) = make_float2(x0, x1);
        }
    }
}

// ---------------------------------------------------------------------------
// Kernel 2: per-chunk decayed A_j[d1][d2] = sum_r gamma^(63-r) K[r][d1] V[r][d2]
// ---------------------------------------------------------------------------
__global__ __launch_bounds__(256) void chunk_stats_kernel() {
    const int j = blockIdx.x;
    const int b = blockIdx.y;
    __shared__ float Ks[CHUNK][DHEAD];
    __shared__ float Vs[CHUNK][DHEAD];

    const int t = threadIdx.x;
    const size_t base = (size_t)(b * L_SEQ + j * CHUNK) * DHEAD;
    for (int i = t; i < CHUNK * DHEAD; i += 256) {
        const int r = i >> 6, d = i & 63;
        const float w = powf(GAMMA_F, (float)(CHUNK - 1 - r));
        Ks[r][d] = g_K[base + i] * w;
        Vs[r][d] = g_V[base + i];
    }
    __syncthreads();

    const int ty = t >> 4, tx = t & 15;
    float acc[4][4];
#pragma unroll
    for (int i = 0; i < 4; i++)
#pragma unroll
        for (int jj = 0; jj < 4; jj++) acc[i][jj] = 0.0f;

    for (int r = 0; r < CHUNK; r++) {
        float a[4], v[4];
#pragma unroll
        for (int i = 0; i < 4; i++) a[i] = Ks[r][ty * 4 + i];
#pragma unroll
        for (int jj = 0; jj < 4; jj++) v[jj] = Vs[r][tx * 4 + jj];
#pragma unroll
        for (int i = 0; i < 4; i++)
#pragma unroll
            for (int jj = 0; jj < 4; jj++) acc[i][jj] = fmaf(a[i], v[jj], acc[i][jj]);
    }

    float* __restrict__ Ap = g_A + (size_t)(b * NCHUNK + j) * DHEAD * DHEAD;
#pragma unroll
    for (int i = 0; i < 4; i++)
#pragma unroll
        for (int jj = 0; jj < 4; jj++)
            Ap[(ty * 4 + i) * DHEAD + tx * 4 + jj] = acc[i][jj];
}

// ---------------------------------------------------------------------------
// Kernel 3: parallel windowed "scan": S_j = sum_{d=1..16} gC^(d-1) A_{j-d}.
// gC^16 ~ 7e-15 -> exact to fp32 noise. Fully parallel (was sequential).
// ---------------------------------------------------------------------------
__global__ __launch_bounds__(256) void window_scan_kernel() {
    const int j = blockIdx.x;
    const int b = blockIdx.y;
    const int t = threadIdx.x;
    const float gC = powf(GAMMA_F, (float)CHUNK);

    float4 s[4];
#pragma unroll
    for (int e = 0; e < 4; e++) s[e] = make_float4(0.f, 0.f, 0.f, 0.f);

    const int dmax = (j < SDEPTH) ? j : SDEPTH;
    float w = 1.0f;
    for (int d = 1; d <= dmax; d++) {
        const float4* Ap = (const float4*)(g_A + (size_t)(b * NCHUNK + j - d) * 4096);
#pragma unroll
        for (int e = 0; e < 4; e++) {
            float4 a = Ap[t + e * 256];
            s[e].x += w * a.x; s[e].y += w * a.y;
            s[e].z += w * a.z; s[e].w += w * a.w;
        }
        w *= gC;
    }
    float4* Sp = (float4*)(g_S + (size_t)(b * NCHUNK + j) * 4096);
#pragma unroll
    for (int e = 0; e < 4; e++) Sp[t + e * 256] = s[e];
}

// ---------------------------------------------------------------------------
// Kernel 4: per-chunk output, split over 2 column halves (blockIdx.z).
// O[r] = sum_{r'<=r} gamma^(r-r') (q_r.k_r') v_r'  +  gamma^(r+1) q_r^T S_j
// ---------------------------------------------------------------------------
__global__ __launch_bounds__(256) void out_kernel(float* __restrict__ O) {
    const int j  = blockIdx.x;
    const int b  = blockIdx.y;
    const int cb = blockIdx.z * 32;   // column base for phases 2/3

    __shared__ float Qs[CHUNK][DHEAD + 1];
    __shared__ float Ks[CHUNK][DHEAD + 1];
    __shared__ float Ps[CHUNK][DHEAD + 1];
    __shared__ float Ts[CHUNK][33];   // V then S (32 cols)
    __shared__ float gpow[CHUNK + 1];

    const int t = threadIdx.x;
    const size_t base = (size_t)(b * L_SEQ + j * CHUNK) * DHEAD;

    for (int i = t; i < CHUNK * DHEAD; i += 256) {
        const int r = i >> 6, d = i & 63;
        Qs[r][d] = g_Q[base + i];
        Ks[r][d] = g_K[base + i];
    }
    if (t <= CHUNK) gpow[t] = powf(GAMMA_F, (float)t);
    __syncthreads();

    const int ty = t >> 4, tx = t & 15;

    // Phase 1: full P = (Q K^T) * decay-mask
    {
        float p[4][4];
#pragma unroll
        for (int i = 0; i < 4; i++)
#pragma unroll
            for (int jj = 0; jj < 4; jj++) p[i][jj] = 0.0f;
        for (int d = 0; d < DHEAD; d++) {
            float q[4], k[4];
#pragma unroll
            for (int i = 0; i < 4; i++) q[i] = Qs[ty * 4 + i][d];
#pragma unroll
            for (int jj = 0; jj < 4; jj++) k[jj] = Ks[tx * 4 + jj][d];
#pragma unroll
            for (int i = 0; i < 4; i++)
#pragma unroll
                for (int jj = 0; jj < 4; jj++) p[i][jj] = fmaf(q[i], k[jj], p[i][jj]);
        }
#pragma unroll
        for (int i = 0; i < 4; i++) {
            const int r = ty * 4 + i;
#pragma unroll
            for (int jj = 0; jj < 4; jj++) {
                const int rp = tx * 4 + jj;
                Ps[r][rp] = (r >= rp) ? p[i][jj] * gpow[r - rp] : 0.0f;
            }
        }
    }
    __syncthreads();

    // Phase 2: O(cols cb..cb+31) = P @ V
    for (int i = t; i < CHUNK * 32; i += 256) {
        const int r = i >> 5, d = i & 31;
        Ts[r][d] = g_V[base + r * DHEAD + cb + d];
    }
    __syncthreads();

    float o[4][2];
#pragma unroll
    for (int i = 0; i < 4; i++) { o[i][0] = 0.f; o[i][1] = 0.f; }

    for (int r2 = 0; r2 < CHUNK; r2++) {
        float pp[4];
#pragma unroll
        for (int i = 0; i < 4; i++) pp[i] = Ps[ty * 4 + i][r2];
        const float v0 = Ts[r2][tx * 2 + 0];
        const float v1 = Ts[r2][tx * 2 + 1];
#pragma unroll
        for (int i = 0; i < 4; i++) {
            o[i][0] = fmaf(pp[i], v0, o[i][0]);
            o[i][1] = fmaf(pp[i], v1, o[i][1]);
        }
    }
    __syncthreads();

    // Phase 3: cross-chunk O += gamma^(r+1) * (Q @ S_j)
    {
        const size_t soff = (size_t)(b * NCHUNK + j) * 4096;
        for (int i = t; i < CHUNK * 32; i += 256) {
            const int r = i >> 5, d = i & 31;
            Ts[r][d] = g_S[soff + r * DHEAD + cb + d];
        }
    }
    __syncthreads();

    float cc[4][2];
#pragma unroll
    for (int i = 0; i < 4; i++) { cc[i][0] = 0.f; cc[i][1] = 0.f; }

    for (int d2 = 0; d2 < DHEAD; d2++) {
        float q[4];
#pragma unroll
        for (int i = 0; i < 4; i++) q[i] = Qs[ty * 4 + i][d2];
        const float s0 = Ts[d2][tx * 2 + 0];
        const float s1 = Ts[d2][tx * 2 + 1];
#pragma unroll
        for (int i = 0; i < 4; i++) {
            cc[i][0] = fmaf(q[i], s0, cc[i][0]);
            cc[i][1] = fmaf(q[i], s1, cc[i][1]);
        }
    }

#pragma unroll
    for (int i = 0; i < 4; i++) {
        const int r = ty * 4 + i;
        const float g = gpow[r + 1];
        const size_t orow = (size_t)(b * L_SEQ + j * CHUNK + r) * DHEAD;
        O[orow + cb + tx * 2 + 0] = o[i][0] + g * cc[i][0];
        O[orow + cb + tx * 2 + 1] = o[i][1] + g * cc[i][1];
    }
}

// ---------------------------------------------------------------------------
extern "C" void kernel_launch(void* const* d_in, const int* in_sizes, int n_in,
                              void* d_out, int out_size) {
    const float* X  = (const float*)d_in[0];
    const float* WQ = (const float*)d_in[1];
    const float* WK = (const float*)d_in[2];
    const float* WV = (const float*)d_in[3];
    float* O = (float*)d_out;

    proj_mma_kernel<<<dim3((BATCH * L_SEQ) / 64, 3), 256>>>(X, WQ, WK, WV);
    chunk_stats_kernel<<<dim3(NCHUNK, BATCH), 256>>>();
    window_scan_kernel<<<dim3(NCHUNK, BATCH), 256>>>();
    out_kernel<<<dim3(NCHUNK, BATCH, 2), 256>>>(O);
}